// round 6
// baseline (speedup 1.0000x reference)
#include <cuda_runtime.h>
#include <cuda_fp16.h>

// Problem constants
#define NCPS 180
#define NCHUNK 9
#define CPN (NCPS / NCHUNK)   // 20 views per chunk
#define DV   96
#define HV   96
#define WV   96
#define HB   560
#define WB   560
#define UE   561   // u entries: up = u0+1 in [0,560]
#define VE   562   // v rows: rp in [0,561]; row rp stores pixel v = rp-1 (halo rows 0 and 561 are zero)
#define ZBLK 4     // z voxels per thread

// Packed u-pair buffer: entry (n, rp, up) = 8 bytes =
// [ half2(c0,c1) @ (v=rp-1, u=up-1), half2(c0,c1) @ (v=rp-1, u=up) ]
// OOB pixels are 0 (matches zeros padding exactly). 454 MB.
__device__ uint2 g_packed[(size_t)NCPS * VE * UE];

__device__ __forceinline__ unsigned int pack_h2(float a, float b) {
    __half2 h = __floats2half2_rn(a, b);
    return *reinterpret_cast<unsigned int*>(&h);
}

// ---------------------------------------------------------------------------
// Prepass chunk: bev (180,2,560,560) f32 -> u-pair fp16 entries for
// n in [n0, n0+CPN). Thread per 8B entry; reads and writes fully coalesced.
// ---------------------------------------------------------------------------
__global__ void __launch_bounds__(256) prepass_kernel(const float* __restrict__ bev,
                                                      int n0) {
    int e = blockIdx.x * 256 + threadIdx.x;
    const int TOTAL = CPN * VE * UE;
    if (e >= TOTAL) return;

    int up = e % UE;            // pixel pair (up-1, up)
    int t  = e / UE;
    int rp = t % VE;            // row rp -> pixel v = rp-1
    int n  = n0 + t / VE;
    int v  = rp - 1;

    float c0a = 0.0f, c1a = 0.0f, c0b = 0.0f, c1b = 0.0f;
    if (v >= 0 && v < HB) {
        const float* b0 = bev + (size_t)n * 2 * HB * WB + (size_t)v * WB;
        const float* b1 = b0 + HB * WB;
        int u0 = up - 1;
        if (u0 >= 0)   { c0a = b0[u0]; c1a = b1[u0]; }
        if (up <= WB-1){ c0b = b0[up]; c1b = b1[up]; }
    }

    uint2 q;
    q.x = pack_h2(c0a, c1a);
    q.y = pack_h2(c0b, c1b);
    g_packed[((size_t)n * VE + rp) * UE + up] = q;
}

// ---------------------------------------------------------------------------
// Project chunk: accumulate views n in [n0, n0+CPN) into out.
// Analytic perspective coordinates (validated R4/R5):
//   ang(n) = ((181+2n)%360)*pi/180 ; rot via smem LUT
//   mag = 1000/(1000+rot_y) ; xs = rot_x*mag*SU + 279.5 ; ys = lz*288*SU*mag + 279.5
// 2 x LDG.64 per sample (rows v0, v0+1 of the u-pair entry).
// ---------------------------------------------------------------------------
__global__ void __launch_bounds__(128, 12) project_kernel(
    float* __restrict__ out, int n0, int first)
{
    __shared__ float2 cs_tab[NCPS];
    for (int n = threadIdx.x; n < NCPS; n += 128) {
        int deg = (181 + 2 * n) % 360;
        float a = (float)((double)deg * 0.017453292519943295);
        float ss, cc;
        sincosf(a, &ss, &cc);          // sin first, cos second
        cs_tab[n] = make_float2(cc, ss);
    }
    __syncthreads();

    int gid = blockIdx.x * 128 + threadIdx.x;   // 96*96*24 threads
    int x  = gid % WV;
    int y  = (gid / WV) % HV;
    int zb = gid / (WV * HV);
    int z0 = zb * ZBLK;

    const float STEP = 2.0f / 95.0f;
    const float SU   = 279.5f / 280.0f;

    float px = fmaf((float)x, STEP, -1.0f) * 288.0f;
    float py = fmaf((float)y, STEP, -1.0f) * 288.0f;

    float lzv[ZBLK];
#pragma unroll
    for (int zi = 0; zi < ZBLK; zi++)
        lzv[zi] = fmaf((float)(z0 + zi), STEP, -1.0f);

    int obase = y * WV + x;

    float acc0[ZBLK], acc1[ZBLK];
    if (first) {
#pragma unroll
        for (int zi = 0; zi < ZBLK; zi++) { acc0[zi] = 0.0f; acc1[zi] = 0.0f; }
    } else {
#pragma unroll
        for (int zi = 0; zi < ZBLK; zi++) {
            acc0[zi] = out[(z0 + zi) * (HV * WV) + obase];
            acc1[zi] = out[(DV * HV * WV) + (z0 + zi) * (HV * WV) + obase];
        }
    }

    for (int n = n0; n < n0 + CPN; n++) {
        float2 cs = cs_tab[n];
        float rot_x = fmaf(px, cs.x,  py * cs.y);
        float rot_y = fmaf(py, cs.x, -px * cs.y);
        float mag   = __fdividef(1000.0f, 1000.0f + rot_y);

        float xs  = fmaf(rot_x * mag, SU, 279.5f);       // pixel u
        float u0f = floorf(xs);
        int   u0  = (int)u0f;
        if (u0 < -1 || u0 > 559) continue;               // u OOB for all z
        float wu1 = xs - u0f;
        float wu0 = 1.0f - wu1;

        float Av = (288.0f * SU) * mag;                  // ys = lz*Av + 279.5

        const uint2* basep = g_packed + (size_t)n * (VE * UE) + (u0 + 1);

#pragma unroll
        for (int zi = 0; zi < ZBLK; zi++) {
            float ys  = fmaf(lzv[zi], Av, 279.5f);
            float v0f = floorf(ys);
            int   v0  = (int)v0f;
            if (v0 >= -1 && v0 <= 559) {
                float wv1 = ys - v0f;
                float wv0 = 1.0f - wv1;
                uint2 q0 = basep[(size_t)(v0 + 1) * UE];   // row v0
                uint2 q1 = basep[(size_t)(v0 + 2) * UE];   // row v0+1
                float2 f00 = __half22float2(*reinterpret_cast<const __half2*>(&q0.x));
                float2 f01 = __half22float2(*reinterpret_cast<const __half2*>(&q0.y));
                float2 f10 = __half22float2(*reinterpret_cast<const __half2*>(&q1.x));
                float2 f11 = __half22float2(*reinterpret_cast<const __half2*>(&q1.y));
                float t0 = fmaf(f00.x, wu0, f01.x * wu1);
                float t1 = fmaf(f00.y, wu0, f01.y * wu1);
                float b0 = fmaf(f10.x, wu0, f11.x * wu1);
                float b1 = fmaf(f10.y, wu0, f11.y * wu1);
                acc0[zi] = fmaf(t0, wv0, fmaf(b0, wv1, acc0[zi]));
                acc1[zi] = fmaf(t1, wv0, fmaf(b1, wv1, acc1[zi]));
            }
        }
    }

    // out layout: (C=2, D, H, W), x fastest
#pragma unroll
    for (int zi = 0; zi < ZBLK; zi++) {
        out[(z0 + zi) * (HV * WV) + obase]                  = acc0[zi];
        out[(DV * HV * WV) + (z0 + zi) * (HV * WV) + obase] = acc1[zi];
    }
}

// ---------------------------------------------------------------------------
// Chunked two-stream pipeline (validated R5 pattern): prepass chunks on a
// forked stream; project chunk k (capture stream) waits on prepass-k event.
// ---------------------------------------------------------------------------
extern "C" void kernel_launch(void* const* d_in, const int* in_sizes, int n_in,
                              void* d_out, int out_size) {
    const float* bev;
    if (in_sizes[0] == 112896000) {
        bev = (const float*)d_in[0];
    } else {
        bev = (const float*)d_in[1];
    }
    float* out = (float*)d_out;

    cudaStream_t s2;
    cudaStreamCreateWithFlags(&s2, cudaStreamNonBlocking);

    cudaEvent_t evFork;
    cudaEventCreateWithFlags(&evFork, cudaEventDisableTiming);
    cudaEventRecord(evFork, 0);            // on capture/default stream
    cudaStreamWaitEvent(s2, evFork, 0);    // fork s2 off it

    const int PCHUNK_E = CPN * VE * UE;    // 20*562*561 = 6,305,640
    const int PBLOCKS  = (PCHUNK_E + 255) / 256;
    const int NTHREADS = WV * HV * (DV / ZBLK);   // 221,184
    const int JBLOCKS  = NTHREADS / 128;          // 1728

    cudaEvent_t evP[NCHUNK];
    for (int k = 0; k < NCHUNK; k++) {
        cudaEventCreateWithFlags(&evP[k], cudaEventDisableTiming);
        prepass_kernel<<<PBLOCKS, 256, 0, s2>>>(bev, k * CPN);
        cudaEventRecord(evP[k], s2);
    }
    for (int k = 0; k < NCHUNK; k++) {
        cudaStreamWaitEvent(0, evP[k], 0);
        project_kernel<<<JBLOCKS, 128>>>(out, k * CPN, k == 0 ? 1 : 0);
    }
    // Join complete: capture stream waits on evP[NCHUNK-1], the last op on s2.
}

// round 7
// speedup vs baseline: 1.1267x; 1.1267x over previous
#include <cuda_runtime.h>
#include <cuda_fp16.h>

// Problem constants
#define NCPS 180
#define NCHUNK 9
#define CPN (NCPS / NCHUNK)   // 20 views per chunk
#define DV   96
#define HV   96
#define WV   96
#define HB   560
#define WB   560
#define UE   561   // u entries: up = u0+1 in [0,560]
#define VE   561   // v rows: vp in [0,560], v0 = vp-1
#define ZBLK 4     // z voxels per thread
#define VSTRIP 4
#define VBLKS 141  // ceil(561/4)

// Packed footprint buffer (16B entry => ONE 32B sector per sample):
// entry (n, vp, up) = [ h2(c0,c1)@(v0,u0), h2@(v0,u0+1), h2@(v0+1,u0), h2@(v0+1,u0+1) ]
// with v0 = vp-1, u0 = up-1. OOB pixels stored as 0 (matches zeros padding).
__device__ uint4 g_packed[(size_t)NCPS * VE * UE];

__device__ __forceinline__ unsigned int pack_h2(float a, float b) {
    __half2 h = __floats2half2_rn(a, b);
    return *reinterpret_cast<unsigned int*>(&h);
}

// ---------------------------------------------------------------------------
// Prepass chunk: each thread builds a 4-row v-strip of entries at one up.
// Input rows are loaded once per strip; the u0=up-1 column comes from
// __shfl_up (lanes are consecutive up within a strip; the up==0 case needs
// zeros anyway, and a warp only straddles strips exactly at up==0).
// ---------------------------------------------------------------------------
__global__ void __launch_bounds__(256) prepass_kernel(const float* __restrict__ bev,
                                                      int n0) {
    const int TOTAL = CPN * VBLKS * UE;
    int e = blockIdx.x * 256 + threadIdx.x;
    bool valid = (e < TOTAL);
    if (!valid) e = TOTAL - 1;        // keep whole warp active for shfl

    int up   = e % UE;
    int t    = e / UE;
    int vblk = t % VBLKS;
    int n    = n0 + t / VBLKS;
    int rp0  = vblk * VSTRIP;
    int lane = threadIdx.x & 31;

    const float* b0 = bev + (size_t)n * 2 * HB * WB;   // channel 0 plane
    const float* b1 = b0 + HB * WB;                    // channel 1 plane

    // cu1[ch][r] = pixel (pv = rp0-1+r, u = up); cu0 = column u = up-1
    float cu1[2][VSTRIP + 1], cu0[2][VSTRIP + 1];
    bool uok1 = (up <= WB - 1);

#pragma unroll
    for (int r = 0; r < VSTRIP + 1; r++) {
        int pv = rp0 - 1 + r;
        bool vok = (pv >= 0) && (pv < HB);
        float a0 = 0.0f, a1 = 0.0f;
        if (vok && uok1) {
            a0 = b0[pv * WB + up];
            a1 = b1[pv * WB + up];
        }
        cu1[0][r] = a0; cu1[1][r] = a1;

        float s0 = __shfl_up_sync(0xffffffffu, a0, 1);
        float s1 = __shfl_up_sync(0xffffffffu, a1, 1);
        if (lane == 0 && up > 0) {       // no lane-1 neighbor: load directly
            s0 = 0.0f; s1 = 0.0f;
            if (vok) { s0 = b0[pv * WB + up - 1]; s1 = b1[pv * WB + up - 1]; }
        }
        if (up == 0) { s0 = 0.0f; s1 = 0.0f; }   // u0 = -1 -> zeros
        cu0[0][r] = s0; cu0[1][r] = s1;
    }

    uint4* dst = g_packed + ((size_t)n * VE + rp0) * UE + up;
#pragma unroll
    for (int j = 0; j < VSTRIP; j++) {
        int rp = rp0 + j;
        if (valid && rp < VE) {
            uint4 q;
            q.x = pack_h2(cu0[0][j],     cu0[1][j]);       // (v0,   u0)
            q.y = pack_h2(cu1[0][j],     cu1[1][j]);       // (v0,   u0+1)
            q.z = pack_h2(cu0[0][j + 1], cu0[1][j + 1]);   // (v0+1, u0)
            q.w = pack_h2(cu1[0][j + 1], cu1[1][j + 1]);   // (v0+1, u0+1)
            dst[(size_t)j * UE] = q;
        }
    }
}

// ---------------------------------------------------------------------------
// Project chunk (validated R5 code): accumulate views [n0, n0+CPN) into out.
// Analytic perspective coordinates; ONE LDG.128 (one 32B sector) per sample.
// ---------------------------------------------------------------------------
__global__ void __launch_bounds__(128, 12) project_kernel(
    float* __restrict__ out, int n0, int first)
{
    __shared__ float2 cs_tab[NCPS];
    for (int n = threadIdx.x; n < NCPS; n += 128) {
        int deg = (181 + 2 * n) % 360;
        float a = (float)((double)deg * 0.017453292519943295);
        float ss, cc;
        sincosf(a, &ss, &cc);          // sin first, cos second
        cs_tab[n] = make_float2(cc, ss);
    }
    __syncthreads();

    int gid = blockIdx.x * 128 + threadIdx.x;   // 96*96*24 threads
    int x  = gid % WV;
    int y  = (gid / WV) % HV;
    int zb = gid / (WV * HV);
    int z0 = zb * ZBLK;

    const float STEP = 2.0f / 95.0f;
    const float SU   = 279.5f / 280.0f;

    float px = fmaf((float)x, STEP, -1.0f) * 288.0f;
    float py = fmaf((float)y, STEP, -1.0f) * 288.0f;

    float lzv[ZBLK];
#pragma unroll
    for (int zi = 0; zi < ZBLK; zi++)
        lzv[zi] = fmaf((float)(z0 + zi), STEP, -1.0f);

    int obase = y * WV + x;

    float acc0[ZBLK], acc1[ZBLK];
    if (first) {
#pragma unroll
        for (int zi = 0; zi < ZBLK; zi++) { acc0[zi] = 0.0f; acc1[zi] = 0.0f; }
    } else {
#pragma unroll
        for (int zi = 0; zi < ZBLK; zi++) {
            acc0[zi] = out[(z0 + zi) * (HV * WV) + obase];
            acc1[zi] = out[(DV * HV * WV) + (z0 + zi) * (HV * WV) + obase];
        }
    }

    for (int n = n0; n < n0 + CPN; n++) {
        float2 cs = cs_tab[n];
        float rot_x = fmaf(px, cs.x,  py * cs.y);
        float rot_y = fmaf(py, cs.x, -px * cs.y);
        float mag   = __fdividef(1000.0f, 1000.0f + rot_y);

        float xs  = fmaf(rot_x * mag, SU, 279.5f);       // pixel u
        float u0f = floorf(xs);
        int   u0  = (int)u0f;
        if (u0 < -1 || u0 > 559) continue;               // u OOB for all z
        float wu1 = xs - u0f;
        float wu0 = 1.0f - wu1;

        float Av = (288.0f * SU) * mag;                  // ys = lz*Av + 279.5

        const uint4* basep = g_packed + (size_t)n * (VE * UE) + (u0 + 1);

#pragma unroll
        for (int zi = 0; zi < ZBLK; zi++) {
            float ys  = fmaf(lzv[zi], Av, 279.5f);
            float v0f = floorf(ys);
            int   v0  = (int)v0f;
            if (v0 >= -1 && v0 <= 559) {
                float wv1 = ys - v0f;
                float wv0 = 1.0f - wv1;
                uint4 q = basep[(size_t)(v0 + 1) * UE];
                float2 f00 = __half22float2(*reinterpret_cast<const __half2*>(&q.x));
                float2 f01 = __half22float2(*reinterpret_cast<const __half2*>(&q.y));
                float2 f10 = __half22float2(*reinterpret_cast<const __half2*>(&q.z));
                float2 f11 = __half22float2(*reinterpret_cast<const __half2*>(&q.w));
                float t0 = fmaf(f00.x, wu0, f01.x * wu1);
                float t1 = fmaf(f00.y, wu0, f01.y * wu1);
                float b0 = fmaf(f10.x, wu0, f11.x * wu1);
                float b1 = fmaf(f10.y, wu0, f11.y * wu1);
                acc0[zi] = fmaf(t0, wv0, fmaf(b0, wv1, acc0[zi]));
                acc1[zi] = fmaf(t1, wv0, fmaf(b1, wv1, acc1[zi]));
            }
        }
    }

    // out layout: (C=2, D, H, W), x fastest
#pragma unroll
    for (int zi = 0; zi < ZBLK; zi++) {
        out[(z0 + zi) * (HV * WV) + obase]                  = acc0[zi];
        out[(DV * HV * WV) + (z0 + zi) * (HV * WV) + obase] = acc1[zi];
    }
}

// ---------------------------------------------------------------------------
// Chunked two-stream pipeline (validated R5 pattern): prepass chunks on a
// forked stream; project chunk k (capture stream) waits on prepass-k event.
// ---------------------------------------------------------------------------
extern "C" void kernel_launch(void* const* d_in, const int* in_sizes, int n_in,
                              void* d_out, int out_size) {
    const float* bev;
    if (in_sizes[0] == 112896000) {
        bev = (const float*)d_in[0];
    } else {
        bev = (const float*)d_in[1];
    }
    float* out = (float*)d_out;

    cudaStream_t s2;
    cudaStreamCreateWithFlags(&s2, cudaStreamNonBlocking);

    cudaEvent_t evFork;
    cudaEventCreateWithFlags(&evFork, cudaEventDisableTiming);
    cudaEventRecord(evFork, 0);            // on capture/default stream
    cudaStreamWaitEvent(s2, evFork, 0);    // fork s2 off it

    const int PCHUNK_T = CPN * VBLKS * UE;        // 20*141*561 = 1,582,020
    const int PBLOCKS  = (PCHUNK_T + 255) / 256;
    const int NTHREADS = WV * HV * (DV / ZBLK);   // 221,184
    const int JBLOCKS  = NTHREADS / 128;          // 1728

    cudaEvent_t evP[NCHUNK];
    for (int k = 0; k < NCHUNK; k++) {
        cudaEventCreateWithFlags(&evP[k], cudaEventDisableTiming);
        prepass_kernel<<<PBLOCKS, 256, 0, s2>>>(bev, k * CPN);
        cudaEventRecord(evP[k], s2);
    }
    for (int k = 0; k < NCHUNK; k++) {
        cudaStreamWaitEvent(0, evP[k], 0);
        project_kernel<<<JBLOCKS, 128>>>(out, k * CPN, k == 0 ? 1 : 0);
    }
    // Join complete: capture stream waits on evP[NCHUNK-1], the last op on s2.
}

// round 8
// speedup vs baseline: 1.1851x; 1.0518x over previous
#include <cuda_runtime.h>
#include <cuda_fp16.h>

// Problem constants
#define NCPS 180
#define NCHUNK 6
#define CPN (NCPS / NCHUNK)   // 30 views per chunk
#define DV   96
#define HV   96
#define WV   96
#define HB   560
#define WB   560
#define UE   561   // u entries: up = u0+1 in [0,560]
#define VE   561   // v rows: vp in [0,560], v0 = vp-1
#define ZBLK 4     // z voxels per thread
#define VSTRIP 8
#define VBLKS 71   // ceil(561/8)

// Packed footprint buffer (16B entry => ONE 32B sector per sample):
// entry (n, vp, up) = [ h2(c0,c1)@(v0,u0), h2@(v0,u0+1), h2@(v0+1,u0), h2@(v0+1,u0+1) ]
// with v0 = vp-1, u0 = up-1. OOB pixels stored as 0 (matches zeros padding).
__device__ uint4 g_packed[(size_t)NCPS * VE * UE];

__device__ __forceinline__ unsigned int pack_h2(float a, float b) {
    __half2 h = __floats2half2_rn(a, b);
    return *reinterpret_cast<unsigned int*>(&h);
}

// ---------------------------------------------------------------------------
// Prepass chunk: each thread builds an 8-row v-strip of entries at one up.
// Input rows loaded once per strip; u0=up-1 column via __shfl_up (lanes are
// consecutive up; up==0 needs zeros anyway; lane 0 loads its neighbor itself).
// ---------------------------------------------------------------------------
__global__ void __launch_bounds__(256) prepass_kernel(const float* __restrict__ bev,
                                                      int n0) {
    const int TOTAL = CPN * VBLKS * UE;
    int e = blockIdx.x * 256 + threadIdx.x;
    bool valid = (e < TOTAL);
    if (!valid) e = TOTAL - 1;        // keep whole warp active for shfl

    int up   = e % UE;
    int t    = e / UE;
    int vblk = t % VBLKS;
    int n    = n0 + t / VBLKS;
    int rp0  = vblk * VSTRIP;
    int lane = threadIdx.x & 31;

    const float* b0 = bev + (size_t)n * 2 * HB * WB;   // channel 0 plane
    const float* b1 = b0 + HB * WB;                    // channel 1 plane

    // cu1[ch][r] = pixel (pv = rp0-1+r, u = up); cu0 = column u = up-1
    float cu1[2][VSTRIP + 1], cu0[2][VSTRIP + 1];
    bool uok1 = (up <= WB - 1);

#pragma unroll
    for (int r = 0; r < VSTRIP + 1; r++) {
        int pv = rp0 - 1 + r;
        bool vok = (pv >= 0) && (pv < HB);
        float a0 = 0.0f, a1 = 0.0f;
        if (vok && uok1) {
            a0 = b0[pv * WB + up];
            a1 = b1[pv * WB + up];
        }
        cu1[0][r] = a0; cu1[1][r] = a1;

        float s0 = __shfl_up_sync(0xffffffffu, a0, 1);
        float s1 = __shfl_up_sync(0xffffffffu, a1, 1);
        if (lane == 0 && up > 0) {       // no lane-1 neighbor: load directly
            s0 = 0.0f; s1 = 0.0f;
            if (vok) { s0 = b0[pv * WB + up - 1]; s1 = b1[pv * WB + up - 1]; }
        }
        if (up == 0) { s0 = 0.0f; s1 = 0.0f; }   // u0 = -1 -> zeros
        cu0[0][r] = s0; cu0[1][r] = s1;
    }

    uint4* dst = g_packed + ((size_t)n * VE + rp0) * UE + up;
#pragma unroll
    for (int j = 0; j < VSTRIP; j++) {
        int rp = rp0 + j;
        if (valid && rp < VE) {
            uint4 q;
            q.x = pack_h2(cu0[0][j],     cu0[1][j]);       // (v0,   u0)
            q.y = pack_h2(cu1[0][j],     cu1[1][j]);       // (v0,   u0+1)
            q.z = pack_h2(cu0[0][j + 1], cu0[1][j + 1]);   // (v0+1, u0)
            q.w = pack_h2(cu1[0][j + 1], cu1[1][j + 1]);   // (v0+1, u0+1)
            dst[(size_t)j * UE] = q;
        }
    }
}

// ---------------------------------------------------------------------------
// Project chunk (validated R5/R7 code): accumulate views [n0, n0+CPN) into
// out. Analytic perspective coordinates; ONE LDG.128 (one sector) per sample.
// ---------------------------------------------------------------------------
__global__ void __launch_bounds__(128, 12) project_kernel(
    float* __restrict__ out, int n0, int first)
{
    __shared__ float2 cs_tab[NCPS];
    for (int n = threadIdx.x; n < NCPS; n += 128) {
        int deg = (181 + 2 * n) % 360;
        float a = (float)((double)deg * 0.017453292519943295);
        float ss, cc;
        sincosf(a, &ss, &cc);          // sin first, cos second
        cs_tab[n] = make_float2(cc, ss);
    }
    __syncthreads();

    int gid = blockIdx.x * 128 + threadIdx.x;   // 96*96*24 threads
    int x  = gid % WV;
    int y  = (gid / WV) % HV;
    int zb = gid / (WV * HV);
    int z0 = zb * ZBLK;

    const float STEP = 2.0f / 95.0f;
    const float SU   = 279.5f / 280.0f;

    float px = fmaf((float)x, STEP, -1.0f) * 288.0f;
    float py = fmaf((float)y, STEP, -1.0f) * 288.0f;

    float lzv[ZBLK];
#pragma unroll
    for (int zi = 0; zi < ZBLK; zi++)
        lzv[zi] = fmaf((float)(z0 + zi), STEP, -1.0f);

    int obase = y * WV + x;

    float acc0[ZBLK], acc1[ZBLK];
    if (first) {
#pragma unroll
        for (int zi = 0; zi < ZBLK; zi++) { acc0[zi] = 0.0f; acc1[zi] = 0.0f; }
    } else {
#pragma unroll
        for (int zi = 0; zi < ZBLK; zi++) {
            acc0[zi] = out[(z0 + zi) * (HV * WV) + obase];
            acc1[zi] = out[(DV * HV * WV) + (z0 + zi) * (HV * WV) + obase];
        }
    }

    for (int n = n0; n < n0 + CPN; n++) {
        float2 cs = cs_tab[n];
        float rot_x = fmaf(px, cs.x,  py * cs.y);
        float rot_y = fmaf(py, cs.x, -px * cs.y);
        float mag   = __fdividef(1000.0f, 1000.0f + rot_y);

        float xs  = fmaf(rot_x * mag, SU, 279.5f);       // pixel u
        float u0f = floorf(xs);
        int   u0  = (int)u0f;
        if (u0 < -1 || u0 > 559) continue;               // u OOB for all z
        float wu1 = xs - u0f;
        float wu0 = 1.0f - wu1;

        float Av = (288.0f * SU) * mag;                  // ys = lz*Av + 279.5

        const uint4* basep = g_packed + (size_t)n * (VE * UE) + (u0 + 1);

#pragma unroll
        for (int zi = 0; zi < ZBLK; zi++) {
            float ys  = fmaf(lzv[zi], Av, 279.5f);
            float v0f = floorf(ys);
            int   v0  = (int)v0f;
            if (v0 >= -1 && v0 <= 559) {
                float wv1 = ys - v0f;
                float wv0 = 1.0f - wv1;
                uint4 q = basep[(size_t)(v0 + 1) * UE];
                float2 f00 = __half22float2(*reinterpret_cast<const __half2*>(&q.x));
                float2 f01 = __half22float2(*reinterpret_cast<const __half2*>(&q.y));
                float2 f10 = __half22float2(*reinterpret_cast<const __half2*>(&q.z));
                float2 f11 = __half22float2(*reinterpret_cast<const __half2*>(&q.w));
                float t0 = fmaf(f00.x, wu0, f01.x * wu1);
                float t1 = fmaf(f00.y, wu0, f01.y * wu1);
                float b0 = fmaf(f10.x, wu0, f11.x * wu1);
                float b1 = fmaf(f10.y, wu0, f11.y * wu1);
                acc0[zi] = fmaf(t0, wv0, fmaf(b0, wv1, acc0[zi]));
                acc1[zi] = fmaf(t1, wv0, fmaf(b1, wv1, acc1[zi]));
            }
        }
    }

    // out layout: (C=2, D, H, W), x fastest
#pragma unroll
    for (int zi = 0; zi < ZBLK; zi++) {
        out[(z0 + zi) * (HV * WV) + obase]                  = acc0[zi];
        out[(DV * HV * WV) + (z0 + zi) * (HV * WV) + obase] = acc1[zi];
    }
}

// ---------------------------------------------------------------------------
// Chunked two-stream pipeline: prepass chunks on a HIGH-PRIORITY forked
// stream (keeps the feed ahead of the 1728-block project chunks); project
// chunk k (capture stream) waits on the prepass-k event.
// ---------------------------------------------------------------------------
extern "C" void kernel_launch(void* const* d_in, const int* in_sizes, int n_in,
                              void* d_out, int out_size) {
    const float* bev;
    if (in_sizes[0] == 112896000) {
        bev = (const float*)d_in[0];
    } else {
        bev = (const float*)d_in[1];
    }
    float* out = (float*)d_out;

    int prLo = 0, prHi = 0;
    cudaDeviceGetStreamPriorityRange(&prLo, &prHi);
    cudaStream_t s2;
    cudaStreamCreateWithPriority(&s2, cudaStreamNonBlocking, prHi);

    cudaEvent_t evFork;
    cudaEventCreateWithFlags(&evFork, cudaEventDisableTiming);
    cudaEventRecord(evFork, 0);            // on capture/default stream
    cudaStreamWaitEvent(s2, evFork, 0);    // fork s2 off it

    const int PCHUNK_T = CPN * VBLKS * UE;        // 30*71*561 = 1,194,930
    const int PBLOCKS  = (PCHUNK_T + 255) / 256;
    const int NTHREADS = WV * HV * (DV / ZBLK);   // 221,184
    const int JBLOCKS  = NTHREADS / 128;          // 1728

    cudaEvent_t evP[NCHUNK];
    for (int k = 0; k < NCHUNK; k++) {
        cudaEventCreateWithFlags(&evP[k], cudaEventDisableTiming);
        prepass_kernel<<<PBLOCKS, 256, 0, s2>>>(bev, k * CPN);
        cudaEventRecord(evP[k], s2);
    }
    for (int k = 0; k < NCHUNK; k++) {
        cudaStreamWaitEvent(0, evP[k], 0);
        project_kernel<<<JBLOCKS, 128>>>(out, k * CPN, k == 0 ? 1 : 0);
    }
    // Join complete: capture stream waits on evP[NCHUNK-1], the last op on s2.
}